// round 14
// baseline (speedup 1.0000x reference)
#include <cuda_runtime.h>
#include <cuda.h>
#include <cuda_fp16.h>
#include <math.h>
#include <stdint.h>

// Problem constants (fixed by the dataset: B=256, D=H=512, lengths=128..383)
#define NN 65408
#define BP 256
#define DD 512
#define HH 512
#define GG 2048
#define TT 383
#define KK 512

// ---------------- device scratch ---------------------------------------------
__device__ __align__(16) __half g_xWH[(size_t)NN * GG];   // gate pre-acts (fp16)
__device__ __align__(16) __half g_flatH[(size_t)NN * HH]; // flat LSTM outputs (fp16)
__device__ __align__(16) float g_att[NN];
__device__ __align__(16) float g_seg[BP * HH];
// h in packed fp16 A-fragment layout, double-buffered
__device__ __align__(16) uint4 g_HF[2][16 * 32 * 32];
// W_hh packed fp16 B-fragment order
__device__ __align__(16) uint2 g_GWH[(size_t)GG * 128];
__device__ int      g_off[BP];
__device__ __align__(128) unsigned g_bar[8 * 128];

__device__ __forceinline__ float sigf(float x) { return 1.0f / (1.0f + expf(-x)); }

__device__ __forceinline__ float tanh_fast(float x) {
    float r; asm("tanh.approx.f32 %0, %1;" : "=f"(r) : "f"(x)); return r;
}
__device__ __forceinline__ float sig_fast(float x) {
    return fmaf(tanh_fast(0.5f * x), 0.5f, 0.5f);
}
__device__ __forceinline__ uint32_t packh2(float a, float b) {
    __half2 h = __floats2half2_rn(a, b);
    uint32_t r; memcpy(&r, &h, 4); return r;
}
__device__ __forceinline__ void mma_f16(float* c,
                                        uint32_t a0, uint32_t a1, uint32_t a2, uint32_t a3,
                                        uint32_t b0, uint32_t b1) {
    asm volatile("mma.sync.aligned.m16n8k16.row.col.f32.f16.f16.f32 "
        "{%0,%1,%2,%3}, {%4,%5,%6,%7}, {%8,%9}, {%0,%1,%2,%3};"
        : "+f"(c[0]), "+f"(c[1]), "+f"(c[2]), "+f"(c[3])
        : "r"(a0), "r"(a1), "r"(a2), "r"(a3), "r"(b0), "r"(b1));
}
__device__ __forceinline__ void bar_arrive(unsigned* p) {
    asm volatile("red.release.gpu.global.add.u32 [%0], 1;" :: "l"(p) : "memory");
}
__device__ __forceinline__ unsigned bar_peek(const unsigned* p) {
    unsigned v;
    asm volatile("ld.acquire.gpu.global.u32 %0, [%1];" : "=r"(v) : "l"(p) : "memory");
    return v;
}
__device__ __forceinline__ uint4 ldcg16(const uint4* p) {
    uint4 v;
    asm volatile("ld.global.cg.v4.u32 {%0,%1,%2,%3}, [%4];"
        : "=r"(v.x), "=r"(v.y), "=r"(v.z), "=r"(v.w) : "l"(p));
    return v;
}

// =================== fp16 mma.sync NT GEMM, templated A/C dtypes ============
// A:[M,512] (fp32 or fp16) row-major, B:[Ncols,512] fp32 row-major.
// C = A @ B^T + bias, stored fp32 or fp16. CTA 128x128, warp 64x32, K-chunk 32.
#define GP16 20
#define STAGE_U (128 * GP16)
#define GEMM_SMEM (4 * STAGE_U * 4)          // 40960 B

template <bool AHALF, bool CHALF>
__global__ void __launch_bounds__(256)
tgemm_f16(const void* __restrict__ Av, const float* __restrict__ Bm,
          const float* __restrict__ bias1, const float* __restrict__ bias2,
          void* __restrict__ Cv, int Ncols) {
    extern __shared__ __align__(16) uint32_t smu[];
    uint32_t* As[2] = { smu,           smu + 2 * STAGE_U };
    uint32_t* Bs[2] = { smu + STAGE_U, smu + 3 * STAGE_U };

    const int tid = threadIdx.x;
    const int wid = tid >> 5, lane = tid & 31;
    const int grp = lane >> 2, tig = lane & 3;
    const int warpM = wid >> 2, warpN = wid & 3;
    const size_t m0 = (size_t)blockIdx.y * 128;
    const int    n0 = blockIdx.x * 128;

    const int lrow = tid >> 1;
    const int lcb  = (tid & 1) * 16;            // element offset within 32-elt chunk row
    const int jb   = (tid & 1) * 8;             // half2 (uint) offset
    const float*  Agf = (const float*)Av + (m0 + lrow) * KK;
    const __half* Agh = (const __half*)Av + (m0 + lrow) * KK;
    const float*  Bg  = Bm + (size_t)(n0 + lrow) * KK;

    float4 ar[4], br[4];
    uint4 arh[2];
    auto ldchunk = [&](int c) {
        if (AHALF) {
            arh[0] = *(const uint4*)&Agh[c * 32 + lcb];
            arh[1] = *(const uint4*)&Agh[c * 32 + lcb + 8];
        } else {
#pragma unroll
            for (int q = 0; q < 4; q++)
                ar[q] = *(const float4*)&Agf[c * 32 + lcb + q * 4];
        }
#pragma unroll
        for (int q = 0; q < 4; q++)
            br[q] = *(const float4*)&Bg[c * 32 + lcb + q * 4];
    };
    auto stchunk = [&](int s) {
        uint32_t* a = As[s] + lrow * GP16 + jb;
        uint32_t* b = Bs[s] + lrow * GP16 + jb;
        if (AHALF) {
            *(uint4*)(a + 0) = arh[0];
            *(uint4*)(a + 4) = arh[1];
        } else {
            uint4 va0 = make_uint4(packh2(ar[0].x, ar[0].y), packh2(ar[0].z, ar[0].w),
                                   packh2(ar[1].x, ar[1].y), packh2(ar[1].z, ar[1].w));
            uint4 va1 = make_uint4(packh2(ar[2].x, ar[2].y), packh2(ar[2].z, ar[2].w),
                                   packh2(ar[3].x, ar[3].y), packh2(ar[3].z, ar[3].w));
            *(uint4*)(a + 0) = va0; *(uint4*)(a + 4) = va1;
        }
        uint4 vb0 = make_uint4(packh2(br[0].x, br[0].y), packh2(br[0].z, br[0].w),
                               packh2(br[1].x, br[1].y), packh2(br[1].z, br[1].w));
        uint4 vb1 = make_uint4(packh2(br[2].x, br[2].y), packh2(br[2].z, br[2].w),
                               packh2(br[3].x, br[3].y), packh2(br[3].z, br[3].w));
        *(uint4*)(b + 0) = vb0; *(uint4*)(b + 4) = vb1;
    };

    float acc[4][4][4];
#pragma unroll
    for (int i = 0; i < 4; i++)
#pragma unroll
        for (int j = 0; j < 4; j++)
#pragma unroll
            for (int k = 0; k < 4; k++) acc[i][j][k] = 0.f;

    ldchunk(0); stchunk(0);
    __syncthreads();

    for (int c = 0; c < KK / 32; c++) {
        const int s = c & 1;
        if (c + 1 < KK / 32) ldchunk(c + 1);

        const uint32_t* Aw = As[s] + (warpM * 64 + grp) * GP16;
        const uint32_t* Bw = Bs[s] + (warpN * 32 + grp) * GP16;
#pragma unroll
        for (int j0 = 0; j0 < 16; j0 += 8) {
            uint32_t af[4][4], bf[4][2];
#pragma unroll
            for (int mf = 0; mf < 4; mf++) {
                const uint32_t* p = Aw + mf * 16 * GP16 + j0;
                af[mf][0] = p[tig];
                af[mf][1] = p[8 * GP16 + tig];
                af[mf][2] = p[tig + 4];
                af[mf][3] = p[8 * GP16 + tig + 4];
            }
#pragma unroll
            for (int nf = 0; nf < 4; nf++) {
                const uint32_t* p = Bw + nf * 8 * GP16 + j0;
                bf[nf][0] = p[tig];
                bf[nf][1] = p[tig + 4];
            }
#pragma unroll
            for (int mf = 0; mf < 4; mf++)
#pragma unroll
                for (int nf = 0; nf < 4; nf++)
                    mma_f16(acc[mf][nf],
                            af[mf][0], af[mf][1], af[mf][2], af[mf][3],
                            bf[nf][0], bf[nf][1]);
        }
        __syncthreads();
        if (c + 1 < KK / 32) { stchunk((c + 1) & 1); __syncthreads(); }
    }

#pragma unroll
    for (int mf = 0; mf < 4; mf++) {
        size_t r0 = m0 + warpM * 64 + mf * 16 + grp;
#pragma unroll
        for (int nf = 0; nf < 4; nf++) {
            int col = n0 + warpN * 32 + nf * 8 + 2 * tig;
            float b0 = bias1[col], b1 = bias1[col + 1];
            if (bias2) { b0 += bias2[col]; b1 += bias2[col + 1]; }
            float c00 = acc[mf][nf][0] + b0, c01 = acc[mf][nf][1] + b1;
            float c10 = acc[mf][nf][2] + b0, c11 = acc[mf][nf][3] + b1;
            if (CHALF) {
                __half* Ch = (__half*)Cv;
                *(uint32_t*)&Ch[r0 * (size_t)Ncols + col]       = packh2(c00, c01);
                *(uint32_t*)&Ch[(r0 + 8) * (size_t)Ncols + col] = packh2(c10, c11);
            } else {
                float* Cf = (float*)Cv;
                *(float2*)&Cf[r0 * (size_t)Ncols + col]       = make_float2(c00, c01);
                *(float2*)&Cf[(r0 + 8) * (size_t)Ncols + col] = make_float2(c10, c11);
            }
        }
    }
}

// ---------------- init --------------------------------------------------------
__global__ void k_init(const int* __restrict__ lengths) {
    int tid = blockIdx.x * blockDim.x + threadIdx.x;
    if (tid < 2 * 16 * 32 * 32 * 4) ((uint32_t*)g_HF)[tid] = 0u;
    if (tid < BP * HH) g_seg[tid] = 0.f;
    if (tid < 8 * 128) g_bar[tid] = 0u;
    if (tid == 0) {
        int acc = 0;
        for (int b = 0; b < BP; b++) { g_off[b] = acc; acc += lengths[b]; }
    }
}

// ---------------- prep: pack W_hh into fp16 B-fragment order ----------------
__global__ void k_prepw(const float* __restrict__ W) {
    int id = blockIdx.x * blockDim.x + threadIdx.x;
    if (id >= GG * 128) return;
    int n = id >> 7;
    int r = id & 127;
    int c = r >> 2, tig = r & 3;
    const float* wr = W + (size_t)n * KK + 16 * c;
    uint2 v;
    v.x = packh2(wr[2 * tig], wr[2 * tig + 1]);
    v.y = packh2(wr[2 * tig + 8], wr[2 * tig + 9]);
    g_GWH[id] = v;
}

// ---------------- persistent LSTM recurrence (fp16 mma, 512 thr) ------------
// W chunks 0..15 live in REGISTERS (64 uint/thread); chunks 16..31 in smem
// (pair-interleaved uint4, pitch 65 -> conflict-free LDS.128).
#define HA_BYTES (2048 * 16)                   // 32768 B
#define GT_PITCH2 136
#define GT_BYTES (32 * GT_PITCH2 * 4)          // 17408 B
#define WS4_U4 (64 * 65)                       // 4160 uint4 = 66560 B
#define PSM5 (HA_BYTES + GT_BYTES + WS4_U4 * 16)  // 116736 B

__global__ void __launch_bounds__(512)
k_lstm_persist(const int* __restrict__ lengths) {
    extern __shared__ __align__(16) char smraw[];
    uint4* HA  = (uint4*)smraw;
    float* GT  = (float*)(smraw + HA_BYTES);
    uint4* WS4 = (uint4*)(smraw + HA_BYTES + GT_BYTES);

    __shared__ int len_s[32];
    __shared__ int off_s[32];
    __shared__ int s_tmax;

    const int tid = threadIdx.x;
    const int pg = blockIdx.x, cg = blockIdx.y;
    const int p0 = pg * 32, hc0 = cg * 32;
    const int wid = tid >> 5, lane = tid & 31;
    const int grp = lane >> 2, tig = lane & 3;
    const int warpM = wid >> 3, warpN = wid & 7;
    unsigned* barp = &g_bar[pg * 128];

    if (wid == 0) {
        int L = lengths[p0 + lane];
        len_s[lane] = L;
        off_s[lane] = g_off[p0 + lane];
        int m = L;
#pragma unroll
        for (int o = 16; o; o >>= 1) m = max(m, __shfl_xor_sync(0xffffffffu, m, o));
        if (lane == 0) s_tmax = m;
    }

    // W rows for this warp
    const int lr0 = warpN * 16 + grp;
    const int lr1 = lr0 + 8;
    const int nrow0 = (lr0 >> 5) * HH + hc0 + (lr0 & 31);
    const int nrow1 = (lr1 >> 5) * HH + hc0 + (lr1 & 31);

    // ---- W chunks 0..15 into registers (loop fully unrolled, const idx) ----
    uint4 Wreg[16];
#pragma unroll
    for (int c = 0; c < 16; c++) {
        uint2 a = g_GWH[((size_t)nrow0 * 32 + c) * 4 + tig];
        uint2 b = g_GWH[((size_t)nrow1 * 32 + c) * 4 + tig];
        Wreg[c] = make_uint4(a.x, a.y, b.x, b.y);
    }

    // ---- W chunks 16..31 into smem, pair-interleaved uint4 ----
#pragma unroll
    for (int i = 0; i < 8; i++) {
        int idx = tid + i * 512;               // 0..4095
        int pr = idx >> 6;
        int rem = idx & 63;
        int cc = rem >> 2, tg = rem & 3;
        int l0 = (pr >> 3) * 16 + (pr & 7);
        int l1 = l0 + 8;
        int n0 = (l0 >> 5) * HH + hc0 + (l0 & 31);
        int n1 = (l1 >> 5) * HH + hc0 + (l1 & 31);
        uint2 a = g_GWH[((size_t)n0 * 32 + cc + 16) * 4 + tg];
        uint2 b = g_GWH[((size_t)n1 * 32 + cc + 16) * 4 + tg];
        WS4[pr * 65 + cc * 4 + tg] = make_uint4(a.x, a.y, b.x, b.y);
    }
    __syncthreads();
    const int tmax = s_tmax;

    const uint4* WSp = WS4 + (size_t)(warpN * 8 + grp) * 65 + tig;

    const int rA = 16 * warpM + grp;
    const uint4* HAw = HA + (size_t)warpM * 1024 + lane;

    const int ep[2] = { tid >> 5, (tid + 512) >> 5 };
    const int eh = tid & 31;
    float creg[2] = { 0.f, 0.f };

    const int kk = hc0 + eh;
    const int kc = kk >> 4, klo = kk & 15;
    const int ktig = (klo & 7) >> 1, ksub = klo & 1, khi = (klo >= 8);
    size_t hoff[2];
#pragma unroll
    for (int s = 0; s < 2; s++) {
        int pl = ep[s];
        int tile_g = pg * 2 + (pl >> 4);
        int r16 = pl & 15;
        int grp8 = r16 & 7, hiM = r16 >> 3;
        int slot = hiM + 2 * khi;
        hoff[s] = ((size_t)(tile_g * 32 + kc) * 32 + grp8 * 4 + ktig) * 16 + slot * 4 + ksub * 2;
    }

    float xg[2][4];
    bool  act[2];
    size_t fis[2];
    auto prefetch_xw = [&](int t) {
#pragma unroll
        for (int s = 0; s < 2; s++) {
            int p = ep[s];
            act[s] = (t < len_s[p]);
            if (act[s]) {
                fis[s] = (size_t)(off_s[p] + t);
                size_t xb = fis[s] * GG + hc0 + eh;
#pragma unroll
                for (int g = 0; g < 4; g++) xg[s][g] = __half2float(g_xWH[xb + g * HH]);
            } else {
                fis[s] = 0;
                xg[s][0] = xg[s][1] = xg[s][2] = xg[s][3] = 0.f;
            }
        }
    };
    prefetch_xw(0);

    for (int t = 0; t < tmax; t++) {
        // ---- fill HA: coalesced copy of pre-packed fp16 h ----
        const uint4* hsrc = &g_HF[t & 1][(size_t)pg * 2048];
#pragma unroll
        for (int i = 0; i < 4; i++) {
            int idx = tid + i * 512;
            HA[idx] = ldcg16(hsrc + idx);
        }
        __syncthreads();

        // ---- 32x128x512 gates GEMM ----
        float acc[2][4];
#pragma unroll
        for (int i = 0; i < 2; i++)
#pragma unroll
            for (int j = 0; j < 4; j++) acc[i][j] = 0.f;

#pragma unroll
        for (int c = 0; c < 16; c++) {         // W from registers
            uint4 Af = HAw[c * 32];
            mma_f16(acc[0], Af.x, Af.y, Af.z, Af.w, Wreg[c].x, Wreg[c].y);
            mma_f16(acc[1], Af.x, Af.y, Af.z, Af.w, Wreg[c].z, Wreg[c].w);
        }
#pragma unroll 8
        for (int c = 16; c < 32; c++) {        // W from smem (1 LDS.128)
            uint4 Af = HAw[c * 32];
            uint4 Wv = WSp[(c - 16) * 4];
            mma_f16(acc[0], Af.x, Af.y, Af.z, Af.w, Wv.x, Wv.y);
            mma_f16(acc[1], Af.x, Af.y, Af.z, Af.w, Wv.z, Wv.w);
        }

        // ---- gate exchange to smem ----
#pragma unroll
        for (int nf = 0; nf < 2; nf++) {
            int cb = warpN * 16 + nf * 8 + 2 * tig;
            *(float2*)&GT[rA * GT_PITCH2 + cb]       = make_float2(acc[nf][0], acc[nf][1]);
            *(float2*)&GT[(rA + 8) * GT_PITCH2 + cb] = make_float2(acc[nf][2], acc[nf][3]);
        }
        __syncthreads();

        // ---- epilogue: fast activations + state update (c in regs) ----
        float hn[2];
        char* hdst = (char*)&g_HF[(t + 1) & 1][0];
#pragma unroll
        for (int s = 0; s < 2; s++) {
            int p = ep[s];
            if (act[s]) {
                float gi = GT[p * GT_PITCH2 + 0 * 32 + eh] + xg[s][0];
                float gf = GT[p * GT_PITCH2 + 1 * 32 + eh] + xg[s][1];
                float gg = GT[p * GT_PITCH2 + 2 * 32 + eh] + xg[s][2];
                float go = GT[p * GT_PITCH2 + 3 * 32 + eh] + xg[s][3];
                float cn = sig_fast(gf) * creg[s] + sig_fast(gi) * tanh_fast(gg);
                hn[s] = sig_fast(go) * tanh_fast(cn);
                creg[s] = cn;
                *(__half*)(hdst + hoff[s]) = __float2half_rn(hn[s]);
            }
        }

        // ---- arrive (release), overlap flat stores + next xW prefetch ----
        __syncthreads();
        if (tid == 0) bar_arrive(barp);
        size_t fsave[2] = { fis[0], fis[1] };
        bool   asave[2] = { act[0], act[1] };
        float  hsave[2] = { hn[0], hn[1] };
        if (t + 1 < tmax) prefetch_xw(t + 1);
#pragma unroll
        for (int s = 0; s < 2; s++)
            if (asave[s]) g_flatH[fsave[s] * HH + hc0 + eh] = __float2half_rn(hsave[s]);
        if (tid == 0) {
            unsigned target = 16u * (unsigned)(t + 1);
            while (bar_peek(barp) < target) __nanosleep(32);
        }
        __syncthreads();
    }
}

// ---------------- attention logits + concrete-relaxation gate ---------------
__global__ void k_att(const float* __restrict__ passedZ,
                      const float* __restrict__ fc2_W, const float* __restrict__ fc2_b,
                      const float* __restrict__ eps_u) {
    int gwarp = (blockIdx.x * blockDim.x + threadIdx.x) >> 5;
    int lane = threadIdx.x & 31;
    if (gwarp >= NN) return;
    const float* row = passedZ + (size_t)gwarp * DD;
    float s = 0.f;
#pragma unroll
    for (int k = lane; k < DD; k += 32) s += row[k] * fc2_W[k];
#pragma unroll
    for (int o = 16; o; o >>= 1) s += __shfl_xor_sync(0xffffffffu, s, o);
    if (lane == 0) {
        float logit = s + fc2_b[0];
        float eu = eps_u[gwarp];
        float eps = (2.0f * 1e-4f - 1.0f) * eu + (1.0f - 1e-4f);
        float gate = logf(eps) - logf(1.0f - eps) + logit;
        g_att[gwarp] = sigf(gate);
    }
}

// ---------------- gated segment sum (flat is fp16 now) ----------------------
__global__ void k_seg(const int* __restrict__ lengths) {
    int b = blockIdx.x;
    int col = threadIdx.x;
    int off = g_off[b];
    int L = lengths[b];
    float acc = 0.f;
    for (int r = 0; r < L; r++) {
        int n = off + r;
        acc += __half2float(g_flatH[(size_t)n * HH + col]) * g_att[n];
    }
    g_seg[(size_t)b * HH + col] = acc;
}

// ---------------- final tiny MLP ---------------------------------------------
__global__ void k_final(const float* __restrict__ mlp1_W, const float* __restrict__ mlp1_b,
                        const float* __restrict__ mlp2_W, const float* __restrict__ mlp2_b,
                        float* __restrict__ out) {
    __shared__ float hidden[16];
    int b = blockIdx.x;
    int tid = threadIdx.x;
    int w = tid >> 5, lane = tid & 31;
    const float* seg = &g_seg[(size_t)b * HH];
    float s = 0.f;
#pragma unroll
    for (int k = lane; k < HH; k += 32) s += seg[k] * mlp1_W[(size_t)w * HH + k];
#pragma unroll
    for (int o = 16; o; o >>= 1) s += __shfl_xor_sync(0xffffffffu, s, o);
    if (lane == 0) hidden[w] = s + mlp1_b[w];
    __syncthreads();
    if (tid < 2) {
        float o = mlp2_b[tid];
#pragma unroll
        for (int j = 0; j < 16; j++) o += hidden[j] * mlp2_W[tid * 16 + j];
        out[b * 2 + tid] = o;
    }
}

// -----------------------------------------------------------------------------
extern "C" void kernel_launch(void* const* d_in, const int* in_sizes, int n_in,
                              void* d_out, int out_size) {
    const float* lstm_input = (const float*)d_in[0];
    const float* eps_u      = (const float*)d_in[1];
    const float* W_ih       = (const float*)d_in[2];
    const float* W_hh       = (const float*)d_in[3];
    const float* b_ih       = (const float*)d_in[4];
    const float* b_hh       = (const float*)d_in[5];
    const float* fc1_W      = (const float*)d_in[6];
    const float* fc1_b      = (const float*)d_in[7];
    const float* fc2_W      = (const float*)d_in[8];
    const float* fc2_b      = (const float*)d_in[9];
    const float* mlp1_W     = (const float*)d_in[10];
    const float* mlp1_b     = (const float*)d_in[11];
    const float* mlp2_W     = (const float*)d_in[12];
    const float* mlp2_b     = (const float*)d_in[13];
    const int*   lengths    = (const int*)d_in[14];

    float* out = (float*)d_out;
    float* passedZ = out + BP * 2;   // tuple order: final[256,2] then passed_Z[N,512]

    __half *xwh, *flath;
    cudaGetSymbolAddress((void**)&xwh, g_xWH);
    cudaGetSymbolAddress((void**)&flath, g_flatH);

    cudaFuncSetAttribute((const void*)tgemm_f16<false, true>,
                         cudaFuncAttributeMaxDynamicSharedMemorySize, GEMM_SMEM);
    cudaFuncSetAttribute((const void*)tgemm_f16<true, false>,
                         cudaFuncAttributeMaxDynamicSharedMemorySize, GEMM_SMEM);
    cudaFuncSetAttribute(k_lstm_persist, cudaFuncAttributeMaxDynamicSharedMemorySize, PSM5);

    // 1. init states/offsets/barriers
    k_init<<<(2 * 16 * 32 * 32 * 4 + 255) / 256, 256>>>(lengths);

    // 2. pack W_hh into fp16 fragment order
    k_prepw<<<(GG * 128 + 255) / 256, 256>>>(W_hh);

    // 3. xW = X @ W_ih^T + b_ih + b_hh   (fp16 MMA, fp32 accum, fp16 store)
    tgemm_f16<false, true><<<dim3(GG / 128, NN / 128), 256, GEMM_SMEM>>>(
        lstm_input, W_ih, b_ih, b_hh, xwh, GG);

    // 4. full LSTM recurrence in ONE persistent launch (fp16 mma, W regs+smem)
    k_lstm_persist<<<dim3(8, 16), 512, PSM5>>>(lengths);

    // 5. passed_Z = flatH(fp16) @ fc1_W^T + fc1_b -> fp32 into d_out
    tgemm_f16<true, false><<<dim3(DD / 128, NN / 128), 256, GEMM_SMEM>>>(
        flath, fc1_W, fc1_b, nullptr, passedZ, DD);

    // 6. attention gate per flat row
    k_att<<<(NN * 32 + 255) / 256, 256>>>(passedZ, fc2_W, fc2_b, eps_u);

    // 7. gated per-person segment sum
    k_seg<<<BP, HH>>>(lengths);

    // 8. final MLP -> out[0:512]
    k_final<<<BP, 512>>>(mlp1_W, mlp1_b, mlp2_W, mlp2_b, out);
}

// round 15
// speedup vs baseline: 1.0016x; 1.0016x over previous
#include <cuda_runtime.h>
#include <cuda.h>
#include <cuda_fp16.h>
#include <math.h>
#include <stdint.h>

// Problem constants (fixed by the dataset: B=256, D=H=512, lengths=128..383)
#define NN 65408
#define BP 256
#define DD 512
#define HH 512
#define GG 2048
#define TT 383
#define KK 512

// ---------------- device scratch ---------------------------------------------
__device__ __align__(16) __half g_xWH[(size_t)NN * GG];   // gate pre-acts (fp16)
__device__ __align__(16) __half g_flatH[(size_t)NN * HH]; // flat LSTM outputs (fp16)
__device__ __align__(16) float g_att[NN];
__device__ __align__(16) float g_seg[BP * HH];
// h in packed fp16 A-fragment layout, double-buffered
__device__ __align__(16) uint4 g_HF[2][16 * 32 * 32];
// W_hh packed fp16 B-fragment order
__device__ __align__(16) uint2 g_GWH[(size_t)GG * 128];
__device__ int      g_off[BP];
__device__ __align__(128) unsigned g_bar[8 * 128];

__device__ __forceinline__ float sigf(float x) { return 1.0f / (1.0f + expf(-x)); }

__device__ __forceinline__ float tanh_fast(float x) {
    float r; asm("tanh.approx.f32 %0, %1;" : "=f"(r) : "f"(x)); return r;
}
__device__ __forceinline__ float sig_fast(float x) {
    return fmaf(tanh_fast(0.5f * x), 0.5f, 0.5f);
}
__device__ __forceinline__ uint32_t packh2(float a, float b) {
    __half2 h = __floats2half2_rn(a, b);
    uint32_t r; memcpy(&r, &h, 4); return r;
}
__device__ __forceinline__ void mma_f16(float* c,
                                        uint32_t a0, uint32_t a1, uint32_t a2, uint32_t a3,
                                        uint32_t b0, uint32_t b1) {
    asm volatile("mma.sync.aligned.m16n8k16.row.col.f32.f16.f16.f32 "
        "{%0,%1,%2,%3}, {%4,%5,%6,%7}, {%8,%9}, {%0,%1,%2,%3};"
        : "+f"(c[0]), "+f"(c[1]), "+f"(c[2]), "+f"(c[3])
        : "r"(a0), "r"(a1), "r"(a2), "r"(a3), "r"(b0), "r"(b1));
}
__device__ __forceinline__ void bar_arrive(unsigned* p) {
    asm volatile("red.release.gpu.global.add.u32 [%0], 1;" :: "l"(p) : "memory");
}
__device__ __forceinline__ unsigned bar_peek(const unsigned* p) {
    unsigned v;
    asm volatile("ld.acquire.gpu.global.u32 %0, [%1];" : "=r"(v) : "l"(p) : "memory");
    return v;
}
__device__ __forceinline__ uint4 ldcg16(const uint4* p) {
    uint4 v;
    asm volatile("ld.global.cg.v4.u32 {%0,%1,%2,%3}, [%4];"
        : "=r"(v.x), "=r"(v.y), "=r"(v.z), "=r"(v.w) : "l"(p));
    return v;
}

// =================== fp16 mma.sync NT GEMM, templated A/C dtypes ============
// A:[M,512] (fp32 or fp16) row-major, B:[Ncols,512] fp32 row-major.
// C = A @ B^T + bias, stored fp32 or fp16. CTA 128x128, warp 64x32, K-chunk 32.
#define GP16 20
#define STAGE_U (128 * GP16)
#define GEMM_SMEM (4 * STAGE_U * 4)          // 40960 B

template <bool AHALF, bool CHALF>
__global__ void __launch_bounds__(256)
tgemm_f16(const void* __restrict__ Av, const float* __restrict__ Bm,
          const float* __restrict__ bias1, const float* __restrict__ bias2,
          void* __restrict__ Cv, int Ncols) {
    extern __shared__ __align__(16) uint32_t smu[];
    uint32_t* As[2] = { smu,           smu + 2 * STAGE_U };
    uint32_t* Bs[2] = { smu + STAGE_U, smu + 3 * STAGE_U };

    const int tid = threadIdx.x;
    const int wid = tid >> 5, lane = tid & 31;
    const int grp = lane >> 2, tig = lane & 3;
    const int warpM = wid >> 2, warpN = wid & 3;
    const size_t m0 = (size_t)blockIdx.y * 128;
    const int    n0 = blockIdx.x * 128;

    const int lrow = tid >> 1;
    const int lcb  = (tid & 1) * 16;
    const int jb   = (tid & 1) * 8;
    const float*  Agf = (const float*)Av + (m0 + lrow) * KK;
    const __half* Agh = (const __half*)Av + (m0 + lrow) * KK;
    const float*  Bg  = Bm + (size_t)(n0 + lrow) * KK;

    float4 ar[4], br[4];
    uint4 arh[2];
    auto ldchunk = [&](int c) {
        if (AHALF) {
            arh[0] = *(const uint4*)&Agh[c * 32 + lcb];
            arh[1] = *(const uint4*)&Agh[c * 32 + lcb + 8];
        } else {
#pragma unroll
            for (int q = 0; q < 4; q++)
                ar[q] = *(const float4*)&Agf[c * 32 + lcb + q * 4];
        }
#pragma unroll
        for (int q = 0; q < 4; q++)
            br[q] = *(const float4*)&Bg[c * 32 + lcb + q * 4];
    };
    auto stchunk = [&](int s) {
        uint32_t* a = As[s] + lrow * GP16 + jb;
        uint32_t* b = Bs[s] + lrow * GP16 + jb;
        if (AHALF) {
            *(uint4*)(a + 0) = arh[0];
            *(uint4*)(a + 4) = arh[1];
        } else {
            uint4 va0 = make_uint4(packh2(ar[0].x, ar[0].y), packh2(ar[0].z, ar[0].w),
                                   packh2(ar[1].x, ar[1].y), packh2(ar[1].z, ar[1].w));
            uint4 va1 = make_uint4(packh2(ar[2].x, ar[2].y), packh2(ar[2].z, ar[2].w),
                                   packh2(ar[3].x, ar[3].y), packh2(ar[3].z, ar[3].w));
            *(uint4*)(a + 0) = va0; *(uint4*)(a + 4) = va1;
        }
        uint4 vb0 = make_uint4(packh2(br[0].x, br[0].y), packh2(br[0].z, br[0].w),
                               packh2(br[1].x, br[1].y), packh2(br[1].z, br[1].w));
        uint4 vb1 = make_uint4(packh2(br[2].x, br[2].y), packh2(br[2].z, br[2].w),
                               packh2(br[3].x, br[3].y), packh2(br[3].z, br[3].w));
        *(uint4*)(b + 0) = vb0; *(uint4*)(b + 4) = vb1;
    };

    float acc[4][4][4];
#pragma unroll
    for (int i = 0; i < 4; i++)
#pragma unroll
        for (int j = 0; j < 4; j++)
#pragma unroll
            for (int k = 0; k < 4; k++) acc[i][j][k] = 0.f;

    ldchunk(0); stchunk(0);
    __syncthreads();

    for (int c = 0; c < KK / 32; c++) {
        const int s = c & 1;
        if (c + 1 < KK / 32) ldchunk(c + 1);

        const uint32_t* Aw = As[s] + (warpM * 64 + grp) * GP16;
        const uint32_t* Bw = Bs[s] + (warpN * 32 + grp) * GP16;
#pragma unroll
        for (int j0 = 0; j0 < 16; j0 += 8) {
            uint32_t af[4][4], bf[4][2];
#pragma unroll
            for (int mf = 0; mf < 4; mf++) {
                const uint32_t* p = Aw + mf * 16 * GP16 + j0;
                af[mf][0] = p[tig];
                af[mf][1] = p[8 * GP16 + tig];
                af[mf][2] = p[tig + 4];
                af[mf][3] = p[8 * GP16 + tig + 4];
            }
#pragma unroll
            for (int nf = 0; nf < 4; nf++) {
                const uint32_t* p = Bw + nf * 8 * GP16 + j0;
                bf[nf][0] = p[tig];
                bf[nf][1] = p[tig + 4];
            }
#pragma unroll
            for (int mf = 0; mf < 4; mf++)
#pragma unroll
                for (int nf = 0; nf < 4; nf++)
                    mma_f16(acc[mf][nf],
                            af[mf][0], af[mf][1], af[mf][2], af[mf][3],
                            bf[nf][0], bf[nf][1]);
        }
        __syncthreads();
        if (c + 1 < KK / 32) { stchunk((c + 1) & 1); __syncthreads(); }
    }

#pragma unroll
    for (int mf = 0; mf < 4; mf++) {
        size_t r0 = m0 + warpM * 64 + mf * 16 + grp;
#pragma unroll
        for (int nf = 0; nf < 4; nf++) {
            int col = n0 + warpN * 32 + nf * 8 + 2 * tig;
            float b0 = bias1[col], b1 = bias1[col + 1];
            if (bias2) { b0 += bias2[col]; b1 += bias2[col + 1]; }
            float c00 = acc[mf][nf][0] + b0, c01 = acc[mf][nf][1] + b1;
            float c10 = acc[mf][nf][2] + b0, c11 = acc[mf][nf][3] + b1;
            if (CHALF) {
                __half* Ch = (__half*)Cv;
                *(uint32_t*)&Ch[r0 * (size_t)Ncols + col]       = packh2(c00, c01);
                *(uint32_t*)&Ch[(r0 + 8) * (size_t)Ncols + col] = packh2(c10, c11);
            } else {
                float* Cf = (float*)Cv;
                *(float2*)&Cf[r0 * (size_t)Ncols + col]       = make_float2(c00, c01);
                *(float2*)&Cf[(r0 + 8) * (size_t)Ncols + col] = make_float2(c10, c11);
            }
        }
    }
}

// ---------------- init --------------------------------------------------------
__global__ void k_init(const int* __restrict__ lengths) {
    int tid = blockIdx.x * blockDim.x + threadIdx.x;
    if (tid < 2 * 16 * 32 * 32 * 4) ((uint32_t*)g_HF)[tid] = 0u;
    if (tid < BP * HH) g_seg[tid] = 0.f;
    if (tid < 8 * 128) g_bar[tid] = 0u;
    if (tid == 0) {
        int acc = 0;
        for (int b = 0; b < BP; b++) { g_off[b] = acc; acc += lengths[b]; }
    }
}

// ---------------- prep: pack W_hh into fp16 B-fragment order ----------------
__global__ void k_prepw(const float* __restrict__ W) {
    int id = blockIdx.x * blockDim.x + threadIdx.x;
    if (id >= GG * 128) return;
    int n = id >> 7;
    int r = id & 127;
    int c = r >> 2, tig = r & 3;
    const float* wr = W + (size_t)n * KK + 16 * c;
    uint2 v;
    v.x = packh2(wr[2 * tig], wr[2 * tig + 1]);
    v.y = packh2(wr[2 * tig + 8], wr[2 * tig + 9]);
    g_GWH[id] = v;
}

// ---------------- persistent LSTM recurrence (fp16 mma, 512 thr) ------------
// R13 structure: FULL W slice resident in smem (regs stay ~65); fp16 xW + flat.
#define WPITCH16 33
#define WH_BYTES (128 * WPITCH16 * 32)                 // 135168 B
#define HA_BYTES (2048 * 16)                           // 32768 B
#define GT_PITCH2 136
#define GT_BYTES (32 * GT_PITCH2 * 4)                  // 17408 B
#define PSM4 (WH_BYTES + HA_BYTES + GT_BYTES)          // 185344 B

__global__ void __launch_bounds__(512)
k_lstm_persist(const int* __restrict__ lengths) {
    extern __shared__ __align__(16) char smraw[];
    uint2* WH = (uint2*)smraw;
    uint4* HA = (uint4*)(smraw + WH_BYTES);
    float* GT = (float*)(smraw + WH_BYTES + HA_BYTES);

    __shared__ int len_s[32];
    __shared__ int off_s[32];
    __shared__ int s_tmax;

    const int tid = threadIdx.x;
    const int pg = blockIdx.x, cg = blockIdx.y;
    const int p0 = pg * 32, hc0 = cg * 32;
    const int wid = tid >> 5, lane = tid & 31;
    const int grp = lane >> 2, tig = lane & 3;
    const int warpM = wid >> 3, warpN = wid & 7;
    unsigned* barp = &g_bar[pg * 128];

    if (wid == 0) {
        int L = lengths[p0 + lane];
        len_s[lane] = L;
        off_s[lane] = g_off[p0 + lane];
        int m = L;
#pragma unroll
        for (int o = 16; o; o >>= 1) m = max(m, __shfl_xor_sync(0xffffffffu, m, o));
        if (lane == 0) s_tmax = m;
    }

    // ---- preload FULL W slice (128 rows x 512 k) as fp16 frags ----
#pragma unroll
    for (int i = 0; i < 16; i++) {
        int gidx = tid + i * 512;
        int lr = gidx >> 6;
        int rem = gidx & 63;
        int c = rem >> 1, hf = rem & 1;
        int n = (lr >> 5) * HH + hc0 + (lr & 31);
        const uint4* src = (const uint4*)g_GWH + ((size_t)(n * 32 + c) * 2 + hf);
        uint4* dst = (uint4*)WH + ((size_t)(lr * WPITCH16 + c) * 2 + hf);
        *dst = *src;
    }
    __syncthreads();
    const int tmax = s_tmax;

    const int lr0 = warpN * 16 + grp;
    const int lr1 = lr0 + 8;
    const uint2* W0p = WH + (size_t)lr0 * WPITCH16 * 4 + tig;
    const uint2* W1p = WH + (size_t)lr1 * WPITCH16 * 4 + tig;

    const int rA = 16 * warpM + grp;
    const uint4* HAw = HA + (size_t)warpM * 1024 + lane;

    const int ep[2] = { tid >> 5, (tid + 512) >> 5 };
    const int eh = tid & 31;
    float creg[2] = { 0.f, 0.f };

    const int kk = hc0 + eh;
    const int kc = kk >> 4, klo = kk & 15;
    const int ktig = (klo & 7) >> 1, ksub = klo & 1, khi = (klo >= 8);
    size_t hoff[2];
#pragma unroll
    for (int s = 0; s < 2; s++) {
        int pl = ep[s];
        int tile_g = pg * 2 + (pl >> 4);
        int r16 = pl & 15;
        int grp8 = r16 & 7, hiM = r16 >> 3;
        int slot = hiM + 2 * khi;
        hoff[s] = ((size_t)(tile_g * 32 + kc) * 32 + grp8 * 4 + ktig) * 16 + slot * 4 + ksub * 2;
    }

    float xg[2][4];
    bool  act[2];
    size_t fis[2];
    auto prefetch_xw = [&](int t) {
#pragma unroll
        for (int s = 0; s < 2; s++) {
            int p = ep[s];
            act[s] = (t < len_s[p]);
            if (act[s]) {
                fis[s] = (size_t)(off_s[p] + t);
                size_t xb = fis[s] * GG + hc0 + eh;
#pragma unroll
                for (int g = 0; g < 4; g++) xg[s][g] = __half2float(g_xWH[xb + g * HH]);
            } else {
                fis[s] = 0;
                xg[s][0] = xg[s][1] = xg[s][2] = xg[s][3] = 0.f;
            }
        }
    };
    prefetch_xw(0);

    for (int t = 0; t < tmax; t++) {
        // ---- fill HA: coalesced copy of pre-packed fp16 h ----
        const uint4* hsrc = &g_HF[t & 1][(size_t)pg * 2048];
#pragma unroll
        for (int i = 0; i < 4; i++) {
            int idx = tid + i * 512;
            HA[idx] = ldcg16(hsrc + idx);
        }
        __syncthreads();

        // ---- 32x128x512 gates GEMM: fp16 m16n8k16, fp32 accum ----
        float acc[2][4];
#pragma unroll
        for (int i = 0; i < 2; i++)
#pragma unroll
            for (int j = 0; j < 4; j++) acc[i][j] = 0.f;

#pragma unroll 8
        for (int c = 0; c < 32; c++) {
            uint4 Af = HAw[c * 32];
            uint2 W0 = W0p[c * 4];
            uint2 W1 = W1p[c * 4];
            mma_f16(acc[0], Af.x, Af.y, Af.z, Af.w, W0.x, W0.y);
            mma_f16(acc[1], Af.x, Af.y, Af.z, Af.w, W1.x, W1.y);
        }

        // ---- gate exchange to smem ----
#pragma unroll
        for (int nf = 0; nf < 2; nf++) {
            int cb = warpN * 16 + nf * 8 + 2 * tig;
            *(float2*)&GT[rA * GT_PITCH2 + cb]       = make_float2(acc[nf][0], acc[nf][1]);
            *(float2*)&GT[(rA + 8) * GT_PITCH2 + cb] = make_float2(acc[nf][2], acc[nf][3]);
        }
        __syncthreads();

        // ---- epilogue: fast activations + state update (c in regs) ----
        float hn[2];
        char* hdst = (char*)&g_HF[(t + 1) & 1][0];
#pragma unroll
        for (int s = 0; s < 2; s++) {
            int p = ep[s];
            if (act[s]) {
                float gi = GT[p * GT_PITCH2 + 0 * 32 + eh] + xg[s][0];
                float gf = GT[p * GT_PITCH2 + 1 * 32 + eh] + xg[s][1];
                float gg = GT[p * GT_PITCH2 + 2 * 32 + eh] + xg[s][2];
                float go = GT[p * GT_PITCH2 + 3 * 32 + eh] + xg[s][3];
                float cn = sig_fast(gf) * creg[s] + sig_fast(gi) * tanh_fast(gg);
                hn[s] = sig_fast(go) * tanh_fast(cn);
                creg[s] = cn;
                *(__half*)(hdst + hoff[s]) = __float2half_rn(hn[s]);
            }
        }

        // ---- arrive (release), overlap flat stores + next xW prefetch ----
        __syncthreads();
        if (tid == 0) bar_arrive(barp);
        size_t fsave[2] = { fis[0], fis[1] };
        bool   asave[2] = { act[0], act[1] };
        float  hsave[2] = { hn[0], hn[1] };
        if (t + 1 < tmax) prefetch_xw(t + 1);
#pragma unroll
        for (int s = 0; s < 2; s++)
            if (asave[s]) g_flatH[fsave[s] * HH + hc0 + eh] = __float2half_rn(hsave[s]);
        if (tid == 0) {
            unsigned target = 16u * (unsigned)(t + 1);
            while (bar_peek(barp) < target) __nanosleep(32);
        }
        __syncthreads();
    }
}

// ---------------- attention logits + concrete-relaxation gate ---------------
__global__ void k_att(const float* __restrict__ passedZ,
                      const float* __restrict__ fc2_W, const float* __restrict__ fc2_b,
                      const float* __restrict__ eps_u) {
    int gwarp = (blockIdx.x * blockDim.x + threadIdx.x) >> 5;
    int lane = threadIdx.x & 31;
    if (gwarp >= NN) return;
    const float* row = passedZ + (size_t)gwarp * DD;
    float s = 0.f;
#pragma unroll
    for (int k = lane; k < DD; k += 32) s += row[k] * fc2_W[k];
#pragma unroll
    for (int o = 16; o; o >>= 1) s += __shfl_xor_sync(0xffffffffu, s, o);
    if (lane == 0) {
        float logit = s + fc2_b[0];
        float eu = eps_u[gwarp];
        float eps = (2.0f * 1e-4f - 1.0f) * eu + (1.0f - 1e-4f);
        float gate = logf(eps) - logf(1.0f - eps) + logit;
        g_att[gwarp] = sigf(gate);
    }
}

// ---------------- gated segment sum (fp16 flat) ------------------------------
__global__ void k_seg(const int* __restrict__ lengths) {
    int b = blockIdx.x;
    int col = threadIdx.x;
    int off = g_off[b];
    int L = lengths[b];
    float acc = 0.f;
    for (int r = 0; r < L; r++) {
        int n = off + r;
        acc += __half2float(g_flatH[(size_t)n * HH + col]) * g_att[n];
    }
    g_seg[(size_t)b * HH + col] = acc;
}

// ---------------- final tiny MLP ---------------------------------------------
__global__ void k_final(const float* __restrict__ mlp1_W, const float* __restrict__ mlp1_b,
                        const float* __restrict__ mlp2_W, const float* __restrict__ mlp2_b,
                        float* __restrict__ out) {
    __shared__ float hidden[16];
    int b = blockIdx.x;
    int tid = threadIdx.x;
    int w = tid >> 5, lane = tid & 31;
    const float* seg = &g_seg[(size_t)b * HH];
    float s = 0.f;
#pragma unroll
    for (int k = lane; k < HH; k += 32) s += seg[k] * mlp1_W[(size_t)w * HH + k];
#pragma unroll
    for (int o = 16; o; o >>= 1) s += __shfl_xor_sync(0xffffffffu, s, o);
    if (lane == 0) hidden[w] = s + mlp1_b[w];
    __syncthreads();
    if (tid < 2) {
        float o = mlp2_b[tid];
#pragma unroll
        for (int j = 0; j < 16; j++) o += hidden[j] * mlp2_W[tid * 16 + j];
        out[b * 2 + tid] = o;
    }
}

// -----------------------------------------------------------------------------
extern "C" void kernel_launch(void* const* d_in, const int* in_sizes, int n_in,
                              void* d_out, int out_size) {
    const float* lstm_input = (const float*)d_in[0];
    const float* eps_u      = (const float*)d_in[1];
    const float* W_ih       = (const float*)d_in[2];
    const float* W_hh       = (const float*)d_in[3];
    const float* b_ih       = (const float*)d_in[4];
    const float* b_hh       = (const float*)d_in[5];
    const float* fc1_W      = (const float*)d_in[6];
    const float* fc1_b      = (const float*)d_in[7];
    const float* fc2_W      = (const float*)d_in[8];
    const float* fc2_b      = (const float*)d_in[9];
    const float* mlp1_W     = (const float*)d_in[10];
    const float* mlp1_b     = (const float*)d_in[11];
    const float* mlp2_W     = (const float*)d_in[12];
    const float* mlp2_b     = (const float*)d_in[13];
    const int*   lengths    = (const int*)d_in[14];

    float* out = (float*)d_out;
    float* passedZ = out + BP * 2;   // tuple order: final[256,2] then passed_Z[N,512]

    __half *xwh, *flath;
    cudaGetSymbolAddress((void**)&xwh, g_xWH);
    cudaGetSymbolAddress((void**)&flath, g_flatH);

    cudaFuncSetAttribute((const void*)tgemm_f16<false, true>,
                         cudaFuncAttributeMaxDynamicSharedMemorySize, GEMM_SMEM);
    cudaFuncSetAttribute((const void*)tgemm_f16<true, false>,
                         cudaFuncAttributeMaxDynamicSharedMemorySize, GEMM_SMEM);
    cudaFuncSetAttribute(k_lstm_persist, cudaFuncAttributeMaxDynamicSharedMemorySize, PSM4);

    // 1. init states/offsets/barriers
    k_init<<<(2 * 16 * 32 * 32 * 4 + 255) / 256, 256>>>(lengths);

    // 2. pack W_hh into fp16 fragment order
    k_prepw<<<(GG * 128 + 255) / 256, 256>>>(W_hh);

    // 3. xW = X @ W_ih^T + b_ih + b_hh   (fp16 MMA, fp32 accum, fp16 store)
    tgemm_f16<false, true><<<dim3(GG / 128, NN / 128), 256, GEMM_SMEM>>>(
        lstm_input, W_ih, b_ih, b_hh, xwh, GG);

    // 4. full LSTM recurrence in ONE persistent launch (fp16 mma, W smem-resident)
    k_lstm_persist<<<dim3(8, 16), 512, PSM4>>>(lengths);

    // 5. passed_Z = flatH(fp16) @ fc1_W^T + fc1_b -> fp32 into d_out
    tgemm_f16<true, false><<<dim3(DD / 128, NN / 128), 256, GEMM_SMEM>>>(
        flath, fc1_W, fc1_b, nullptr, passedZ, DD);

    // 6. attention gate per flat row
    k_att<<<(NN * 32 + 255) / 256, 256>>>(passedZ, fc2_W, fc2_b, eps_u);

    // 7. gated per-person segment sum
    k_seg<<<BP, HH>>>(lengths);

    // 8. final MLP -> out[0:512]
    k_final<<<BP, 512>>>(mlp1_W, mlp1_b, mlp2_W, mlp2_b, out);
}

// round 16
// speedup vs baseline: 1.1050x; 1.1032x over previous
#include <cuda_runtime.h>
#include <cuda.h>
#include <cuda_fp16.h>
#include <math.h>
#include <stdint.h>

// Problem constants (fixed by the dataset: B=256, D=H=512, lengths=128..383)
#define NN 65408
#define BP 256
#define DD 512
#define HH 512
#define GG 2048
#define TT 383
#define KK 512

// ---------------- device scratch ---------------------------------------------
__device__ __align__(16) float g_xW[(size_t)NN * GG];     // gate pre-acts (fp32)
__device__ __align__(16) float g_flat[(size_t)NN * HH];   // flat LSTM outputs (fp32)
__device__ __align__(16) float g_att[NN];
__device__ __align__(16) float g_logit[NN];
__device__ __align__(16) float g_seg[BP * HH];
// h in packed fp16 A-fragment layout, double-buffered
__device__ __align__(16) uint4 g_HF[2][16 * 32 * 32];
// W_hh packed fp16 B-fragment order
__device__ __align__(16) uint2 g_GWH[(size_t)GG * 128];
__device__ int      g_off[BP];
__device__ __align__(128) unsigned g_bar[8 * 128];

__device__ __forceinline__ float sigf(float x) { return 1.0f / (1.0f + expf(-x)); }

__device__ __forceinline__ float tanh_fast(float x) {
    float r; asm("tanh.approx.f32 %0, %1;" : "=f"(r) : "f"(x)); return r;
}
__device__ __forceinline__ float sig_fast(float x) {
    return fmaf(tanh_fast(0.5f * x), 0.5f, 0.5f);
}
__device__ __forceinline__ uint32_t packh2(float a, float b) {
    __half2 h = __floats2half2_rn(a, b);
    uint32_t r; memcpy(&r, &h, 4); return r;
}
__device__ __forceinline__ void mma_f16(float* c,
                                        uint32_t a0, uint32_t a1, uint32_t a2, uint32_t a3,
                                        uint32_t b0, uint32_t b1) {
    asm volatile("mma.sync.aligned.m16n8k16.row.col.f32.f16.f16.f32 "
        "{%0,%1,%2,%3}, {%4,%5,%6,%7}, {%8,%9}, {%0,%1,%2,%3};"
        : "+f"(c[0]), "+f"(c[1]), "+f"(c[2]), "+f"(c[3])
        : "r"(a0), "r"(a1), "r"(a2), "r"(a3), "r"(b0), "r"(b1));
}
__device__ __forceinline__ void bar_arrive(unsigned* p) {
    asm volatile("red.release.gpu.global.add.u32 [%0], 1;" :: "l"(p) : "memory");
}
__device__ __forceinline__ unsigned bar_peek(const unsigned* p) {
    unsigned v;
    asm volatile("ld.acquire.gpu.global.u32 %0, [%1];" : "=r"(v) : "l"(p) : "memory");
    return v;
}
__device__ __forceinline__ uint4 ldcg16(const uint4* p) {
    uint4 v;
    asm volatile("ld.global.cg.v4.u32 {%0,%1,%2,%3}, [%4];"
        : "=r"(v.x), "=r"(v.y), "=r"(v.z), "=r"(v.w) : "l"(p));
    return v;
}

// =================== fp16 mma.sync NT GEMM: C = A @ B^T + bias ==============
// A:[M,512] fp32 row-major, B:[Ncols,512] fp32 row-major; cvt to fp16 at smem
// store. CTA 128x128, warp 64x32, K-chunk 32 double-buffered.
// Optional fused logit: logit_out[row] += sum_col C[row,col]*logitW[col].
#define GP16 20
#define STAGE_U (128 * GP16)
#define GEMM_SMEM (4 * STAGE_U * 4)          // 40960 B

__global__ void __launch_bounds__(256)
tgemm_f16(const float* __restrict__ A, const float* __restrict__ Bm,
          const float* __restrict__ bias1, const float* __restrict__ bias2,
          float* __restrict__ C, int Ncols,
          const float* __restrict__ logitW, float* __restrict__ logit_out) {
    extern __shared__ __align__(16) uint32_t smu[];
    uint32_t* As[2] = { smu,           smu + 2 * STAGE_U };
    uint32_t* Bs[2] = { smu + STAGE_U, smu + 3 * STAGE_U };

    const int tid = threadIdx.x;
    const int wid = tid >> 5, lane = tid & 31;
    const int grp = lane >> 2, tig = lane & 3;
    const int warpM = wid >> 2, warpN = wid & 3;
    const size_t m0 = (size_t)blockIdx.y * 128;
    const int    n0 = blockIdx.x * 128;

    const int lrow = tid >> 1;
    const int lcb  = (tid & 1) * 16;
    const int jb   = (tid & 1) * 8;
    const float* Ag = A  + (m0 + lrow) * KK;
    const float* Bg = Bm + (size_t)(n0 + lrow) * KK;

    float4 ar[4], br[4];
    auto ldchunk = [&](int c) {
#pragma unroll
        for (int q = 0; q < 4; q++) {
            ar[q] = *(const float4*)&Ag[c * 32 + lcb + q * 4];
            br[q] = *(const float4*)&Bg[c * 32 + lcb + q * 4];
        }
    };
    auto stchunk = [&](int s) {
        uint32_t* a = As[s] + lrow * GP16 + jb;
        uint32_t* b = Bs[s] + lrow * GP16 + jb;
        uint4 va0 = make_uint4(packh2(ar[0].x, ar[0].y), packh2(ar[0].z, ar[0].w),
                               packh2(ar[1].x, ar[1].y), packh2(ar[1].z, ar[1].w));
        uint4 va1 = make_uint4(packh2(ar[2].x, ar[2].y), packh2(ar[2].z, ar[2].w),
                               packh2(ar[3].x, ar[3].y), packh2(ar[3].z, ar[3].w));
        uint4 vb0 = make_uint4(packh2(br[0].x, br[0].y), packh2(br[0].z, br[0].w),
                               packh2(br[1].x, br[1].y), packh2(br[1].z, br[1].w));
        uint4 vb1 = make_uint4(packh2(br[2].x, br[2].y), packh2(br[2].z, br[2].w),
                               packh2(br[3].x, br[3].y), packh2(br[3].z, br[3].w));
        *(uint4*)(a + 0) = va0; *(uint4*)(a + 4) = va1;
        *(uint4*)(b + 0) = vb0; *(uint4*)(b + 4) = vb1;
    };

    float acc[4][4][4];
#pragma unroll
    for (int i = 0; i < 4; i++)
#pragma unroll
        for (int j = 0; j < 4; j++)
#pragma unroll
            for (int k = 0; k < 4; k++) acc[i][j][k] = 0.f;

    ldchunk(0); stchunk(0);
    __syncthreads();

    for (int c = 0; c < KK / 32; c++) {
        const int s = c & 1;
        if (c + 1 < KK / 32) ldchunk(c + 1);

        const uint32_t* Aw = As[s] + (warpM * 64 + grp) * GP16;
        const uint32_t* Bw = Bs[s] + (warpN * 32 + grp) * GP16;
#pragma unroll
        for (int j0 = 0; j0 < 16; j0 += 8) {
            uint32_t af[4][4], bf[4][2];
#pragma unroll
            for (int mf = 0; mf < 4; mf++) {
                const uint32_t* p = Aw + mf * 16 * GP16 + j0;
                af[mf][0] = p[tig];
                af[mf][1] = p[8 * GP16 + tig];
                af[mf][2] = p[tig + 4];
                af[mf][3] = p[8 * GP16 + tig + 4];
            }
#pragma unroll
            for (int nf = 0; nf < 4; nf++) {
                const uint32_t* p = Bw + nf * 8 * GP16 + j0;
                bf[nf][0] = p[tig];
                bf[nf][1] = p[tig + 4];
            }
#pragma unroll
            for (int mf = 0; mf < 4; mf++)
#pragma unroll
                for (int nf = 0; nf < 4; nf++)
                    mma_f16(acc[mf][nf],
                            af[mf][0], af[mf][1], af[mf][2], af[mf][3],
                            bf[nf][0], bf[nf][1]);
        }
        __syncthreads();
        if (c + 1 < KK / 32) { stchunk((c + 1) & 1); __syncthreads(); }
    }

#pragma unroll
    for (int mf = 0; mf < 4; mf++) {
        size_t r0 = m0 + warpM * 64 + mf * 16 + grp;
        float p0 = 0.f, p1 = 0.f;   // fused logit partials for rows r0, r0+8
#pragma unroll
        for (int nf = 0; nf < 4; nf++) {
            int col = n0 + warpN * 32 + nf * 8 + 2 * tig;
            float b0 = bias1[col], b1 = bias1[col + 1];
            if (bias2) { b0 += bias2[col]; b1 += bias2[col + 1]; }
            float c00 = acc[mf][nf][0] + b0, c01 = acc[mf][nf][1] + b1;
            float c10 = acc[mf][nf][2] + b0, c11 = acc[mf][nf][3] + b1;
            *(float2*)&C[r0 * (size_t)Ncols + col]       = make_float2(c00, c01);
            *(float2*)&C[(r0 + 8) * (size_t)Ncols + col] = make_float2(c10, c11);
            if (logitW) {
                float w0 = logitW[col], w1 = logitW[col + 1];
                p0 = fmaf(c00, w0, fmaf(c01, w1, p0));
                p1 = fmaf(c10, w0, fmaf(c11, w1, p1));
            }
        }
        if (logitW) {
            // reduce over the 4 lanes of the quad (tig 0..3)
            p0 += __shfl_xor_sync(0xffffffffu, p0, 1);
            p0 += __shfl_xor_sync(0xffffffffu, p0, 2);
            p1 += __shfl_xor_sync(0xffffffffu, p1, 1);
            p1 += __shfl_xor_sync(0xffffffffu, p1, 2);
            if (tig == 0) {
                atomicAdd(&logit_out[r0], p0);
                atomicAdd(&logit_out[r0 + 8], p1);
            }
        }
    }
}

// ---------------- init --------------------------------------------------------
__global__ void k_init(const int* __restrict__ lengths) {
    int tid = blockIdx.x * blockDim.x + threadIdx.x;
    if (tid < 2 * 16 * 32 * 32 * 4) ((uint32_t*)g_HF)[tid] = 0u;
    if (tid < BP * HH) g_seg[tid] = 0.f;
    if (tid < NN) g_logit[tid] = 0.f;
    if (tid < 8 * 128) g_bar[tid] = 0u;
    if (tid == 0) {
        int acc = 0;
        for (int b = 0; b < BP; b++) { g_off[b] = acc; acc += lengths[b]; }
    }
}

// ---------------- prep: pack W_hh into fp16 B-fragment order ----------------
__global__ void k_prepw(const float* __restrict__ W) {
    int id = blockIdx.x * blockDim.x + threadIdx.x;
    if (id >= GG * 128) return;
    int n = id >> 7;
    int r = id & 127;
    int c = r >> 2, tig = r & 3;
    const float* wr = W + (size_t)n * KK + 16 * c;
    uint2 v;
    v.x = packh2(wr[2 * tig], wr[2 * tig + 1]);
    v.y = packh2(wr[2 * tig + 8], wr[2 * tig + 9]);
    g_GWH[id] = v;
}

// ---------------- persistent LSTM recurrence (fp16 mma, 512 thr) ------------
// R13 structure: FULL W slice resident in smem; fp32 xW/flat.
#define WPITCH16 33
#define WH_BYTES (128 * WPITCH16 * 32)                 // 135168 B
#define HA_BYTES (2048 * 16)                           // 32768 B
#define GT_PITCH2 136
#define GT_BYTES (32 * GT_PITCH2 * 4)                  // 17408 B
#define PSM4 (WH_BYTES + HA_BYTES + GT_BYTES)          // 185344 B

__global__ void __launch_bounds__(512)
k_lstm_persist(const int* __restrict__ lengths) {
    extern __shared__ __align__(16) char smraw[];
    uint2* WH = (uint2*)smraw;
    uint4* HA = (uint4*)(smraw + WH_BYTES);
    float* GT = (float*)(smraw + WH_BYTES + HA_BYTES);

    __shared__ int len_s[32];
    __shared__ int off_s[32];
    __shared__ int s_tmax;

    const int tid = threadIdx.x;
    const int pg = blockIdx.x, cg = blockIdx.y;
    const int p0 = pg * 32, hc0 = cg * 32;
    const int wid = tid >> 5, lane = tid & 31;
    const int grp = lane >> 2, tig = lane & 3;
    const int warpM = wid >> 3, warpN = wid & 7;
    unsigned* barp = &g_bar[pg * 128];

    if (wid == 0) {
        int L = lengths[p0 + lane];
        len_s[lane] = L;
        off_s[lane] = g_off[p0 + lane];
        int m = L;
#pragma unroll
        for (int o = 16; o; o >>= 1) m = max(m, __shfl_xor_sync(0xffffffffu, m, o));
        if (lane == 0) s_tmax = m;
    }

    // ---- preload FULL W slice (128 rows x 512 k) as fp16 frags ----
#pragma unroll
    for (int i = 0; i < 16; i++) {
        int gidx = tid + i * 512;
        int lr = gidx >> 6;
        int rem = gidx & 63;
        int c = rem >> 1, hf = rem & 1;
        int n = (lr >> 5) * HH + hc0 + (lr & 31);
        const uint4* src = (const uint4*)g_GWH + ((size_t)(n * 32 + c) * 2 + hf);
        uint4* dst = (uint4*)WH + ((size_t)(lr * WPITCH16 + c) * 2 + hf);
        *dst = *src;
    }
    __syncthreads();
    const int tmax = s_tmax;

    const int lr0 = warpN * 16 + grp;
    const int lr1 = lr0 + 8;
    const uint2* W0p = WH + (size_t)lr0 * WPITCH16 * 4 + tig;
    const uint2* W1p = WH + (size_t)lr1 * WPITCH16 * 4 + tig;

    const int rA = 16 * warpM + grp;
    const uint4* HAw = HA + (size_t)warpM * 1024 + lane;

    const int ep[2] = { tid >> 5, (tid + 512) >> 5 };
    const int eh = tid & 31;
    float creg[2] = { 0.f, 0.f };

    const int kk = hc0 + eh;
    const int kc = kk >> 4, klo = kk & 15;
    const int ktig = (klo & 7) >> 1, ksub = klo & 1, khi = (klo >= 8);
    size_t hoff[2];
#pragma unroll
    for (int s = 0; s < 2; s++) {
        int pl = ep[s];
        int tile_g = pg * 2 + (pl >> 4);
        int r16 = pl & 15;
        int grp8 = r16 & 7, hiM = r16 >> 3;
        int slot = hiM + 2 * khi;
        hoff[s] = ((size_t)(tile_g * 32 + kc) * 32 + grp8 * 4 + ktig) * 16 + slot * 4 + ksub * 2;
    }

    float xg[2][4];
    bool  act[2];
    size_t fis[2];
    auto prefetch_xw = [&](int t) {
#pragma unroll
        for (int s = 0; s < 2; s++) {
            int p = ep[s];
            act[s] = (t < len_s[p]);
            if (act[s]) {
                fis[s] = (size_t)(off_s[p] + t);
                size_t xb = fis[s] * GG + hc0 + eh;
#pragma unroll
                for (int g = 0; g < 4; g++) xg[s][g] = __ldcg(&g_xW[xb + g * HH]);
            } else {
                fis[s] = 0;
                xg[s][0] = xg[s][1] = xg[s][2] = xg[s][3] = 0.f;
            }
        }
    };
    prefetch_xw(0);

    for (int t = 0; t < tmax; t++) {
        // ---- fill HA: coalesced copy of pre-packed fp16 h ----
        const uint4* hsrc = &g_HF[t & 1][(size_t)pg * 2048];
#pragma unroll
        for (int i = 0; i < 4; i++) {
            int idx = tid + i * 512;
            HA[idx] = ldcg16(hsrc + idx);
        }
        __syncthreads();

        // ---- 32x128x512 gates GEMM: fp16 m16n8k16, fp32 accum ----
        float acc[2][4];
#pragma unroll
        for (int i = 0; i < 2; i++)
#pragma unroll
            for (int j = 0; j < 4; j++) acc[i][j] = 0.f;

#pragma unroll 8
        for (int c = 0; c < 32; c++) {
            uint4 Af = HAw[c * 32];
            uint2 W0 = W0p[c * 4];
            uint2 W1 = W1p[c * 4];
            mma_f16(acc[0], Af.x, Af.y, Af.z, Af.w, W0.x, W0.y);
            mma_f16(acc[1], Af.x, Af.y, Af.z, Af.w, W1.x, W1.y);
        }

        // ---- gate exchange to smem ----
#pragma unroll
        for (int nf = 0; nf < 2; nf++) {
            int cb = warpN * 16 + nf * 8 + 2 * tig;
            *(float2*)&GT[rA * GT_PITCH2 + cb]       = make_float2(acc[nf][0], acc[nf][1]);
            *(float2*)&GT[(rA + 8) * GT_PITCH2 + cb] = make_float2(acc[nf][2], acc[nf][3]);
        }
        __syncthreads();

        // ---- epilogue: fast activations + state update (c in regs) ----
        float hn[2];
        char* hdst = (char*)&g_HF[(t + 1) & 1][0];
#pragma unroll
        for (int s = 0; s < 2; s++) {
            int p = ep[s];
            if (act[s]) {
                float gi = GT[p * GT_PITCH2 + 0 * 32 + eh] + xg[s][0];
                float gf = GT[p * GT_PITCH2 + 1 * 32 + eh] + xg[s][1];
                float gg = GT[p * GT_PITCH2 + 2 * 32 + eh] + xg[s][2];
                float go = GT[p * GT_PITCH2 + 3 * 32 + eh] + xg[s][3];
                float cn = sig_fast(gf) * creg[s] + sig_fast(gi) * tanh_fast(gg);
                hn[s] = sig_fast(go) * tanh_fast(cn);
                creg[s] = cn;
                *(__half*)(hdst + hoff[s]) = __float2half_rn(hn[s]);
            }
        }

        // ---- arrive (release), overlap flat stores + next xW prefetch ----
        __syncthreads();
        if (tid == 0) bar_arrive(barp);
        size_t fsave[2] = { fis[0], fis[1] };
        bool   asave[2] = { act[0], act[1] };
        float  hsave[2] = { hn[0], hn[1] };
        if (t + 1 < tmax) prefetch_xw(t + 1);
#pragma unroll
        for (int s = 0; s < 2; s++)
            if (asave[s]) g_flat[fsave[s] * HH + hc0 + eh] = hsave[s];
        if (tid == 0) {
            unsigned target = 16u * (unsigned)(t + 1);
            while (bar_peek(barp) < target) __nanosleep(32);
        }
        __syncthreads();
    }
}

// ---------------- attention gate (elementwise; logit pre-computed) ----------
__global__ void k_att(const float* __restrict__ fc2_b, const float* __restrict__ eps_u) {
    int n = blockIdx.x * blockDim.x + threadIdx.x;
    if (n >= NN) return;
    float logit = g_logit[n] + fc2_b[0];
    float eu = eps_u[n];
    float eps = (2.0f * 1e-4f - 1.0f) * eu + (1.0f - 1e-4f);
    float gate = logf(eps) - logf(1.0f - eps) + logit;
    g_att[n] = sigf(gate);
}

// ---------------- gated segment sum (8-way split + atomic accumulate) -------
__global__ void k_seg(const int* __restrict__ lengths) {
    int b = blockIdx.x;
    int chunk = blockIdx.y;          // 0..7
    int col = threadIdx.x;           // 512
    int off = g_off[b];
    int L = lengths[b];
    int r0 = (L * chunk) >> 3;
    int r1 = (L * (chunk + 1)) >> 3;
    float acc = 0.f;
    for (int r = r0; r < r1; r++) {
        int n = off + r;
        acc += g_flat[(size_t)n * HH + col] * g_att[n];
    }
    atomicAdd(&g_seg[(size_t)b * HH + col], acc);
}

// ---------------- final tiny MLP ---------------------------------------------
__global__ void k_final(const float* __restrict__ mlp1_W, const float* __restrict__ mlp1_b,
                        const float* __restrict__ mlp2_W, const float* __restrict__ mlp2_b,
                        float* __restrict__ out) {
    __shared__ float hidden[16];
    int b = blockIdx.x;
    int tid = threadIdx.x;
    int w = tid >> 5, lane = tid & 31;
    const float* seg = &g_seg[(size_t)b * HH];
    float s = 0.f;
#pragma unroll
    for (int k = lane; k < HH; k += 32) s += seg[k] * mlp1_W[(size_t)w * HH + k];
#pragma unroll
    for (int o = 16; o; o >>= 1) s += __shfl_xor_sync(0xffffffffu, s, o);
    if (lane == 0) hidden[w] = s + mlp1_b[w];
    __syncthreads();
    if (tid < 2) {
        float o = mlp2_b[tid];
#pragma unroll
        for (int j = 0; j < 16; j++) o += hidden[j] * mlp2_W[tid * 16 + j];
        out[b * 2 + tid] = o;
    }
}

// -----------------------------------------------------------------------------
extern "C" void kernel_launch(void* const* d_in, const int* in_sizes, int n_in,
                              void* d_out, int out_size) {
    const float* lstm_input = (const float*)d_in[0];
    const float* eps_u      = (const float*)d_in[1];
    const float* W_ih       = (const float*)d_in[2];
    const float* W_hh       = (const float*)d_in[3];
    const float* b_ih       = (const float*)d_in[4];
    const float* b_hh       = (const float*)d_in[5];
    const float* fc1_W      = (const float*)d_in[6];
    const float* fc1_b      = (const float*)d_in[7];
    const float* fc2_W      = (const float*)d_in[8];
    const float* fc2_b      = (const float*)d_in[9];
    const float* mlp1_W     = (const float*)d_in[10];
    const float* mlp1_b     = (const float*)d_in[11];
    const float* mlp2_W     = (const float*)d_in[12];
    const float* mlp2_b     = (const float*)d_in[13];
    const int*   lengths    = (const int*)d_in[14];

    float* out = (float*)d_out;
    float* passedZ = out + BP * 2;   // tuple order: final[256,2] then passed_Z[N,512]

    float *xw, *flat, *logit;
    cudaGetSymbolAddress((void**)&xw, g_xW);
    cudaGetSymbolAddress((void**)&flat, g_flat);
    cudaGetSymbolAddress((void**)&logit, g_logit);

    cudaFuncSetAttribute(tgemm_f16, cudaFuncAttributeMaxDynamicSharedMemorySize, GEMM_SMEM);
    cudaFuncSetAttribute(k_lstm_persist, cudaFuncAttributeMaxDynamicSharedMemorySize, PSM4);

    // 1. init states/offsets/barriers/logits
    k_init<<<(2 * 16 * 32 * 32 * 4 + 255) / 256, 256>>>(lengths);

    // 2. pack W_hh into fp16 fragment order
    k_prepw<<<(GG * 128 + 255) / 256, 256>>>(W_hh);

    // 3. xW = X @ W_ih^T + b_ih + b_hh   (fp16 MMA, fp32 accum/store)
    tgemm_f16<<<dim3(GG / 128, NN / 128), 256, GEMM_SMEM>>>(
        lstm_input, W_ih, b_ih, b_hh, xw, GG, nullptr, nullptr);

    // 4. full LSTM recurrence in ONE persistent launch (fp16 mma, W smem-resident)
    k_lstm_persist<<<dim3(8, 16), 512, PSM4>>>(lengths);

    // 5. passed_Z = flat @ fc1_W^T + fc1_b -> d_out, with FUSED att-logit dot
    tgemm_f16<<<dim3(DD / 128, NN / 128), 256, GEMM_SMEM>>>(
        flat, fc1_W, fc1_b, nullptr, passedZ, DD, fc2_W, logit);

    // 6. attention gate per flat row (elementwise now)
    k_att<<<(NN + 255) / 256, 256>>>(fc2_b, eps_u);

    // 7. gated per-person segment sum (8-way parallel)
    k_seg<<<dim3(BP, 8), HH>>>(lengths);

    // 8. final MLP -> out[0:512]
    k_final<<<BP, 512>>>(mlp1_W, mlp1_b, mlp2_W, mlp2_b, out);
}

// round 17
// speedup vs baseline: 1.1080x; 1.0027x over previous
#include <cuda_runtime.h>
#include <cuda.h>
#include <cuda_fp16.h>
#include <math.h>
#include <stdint.h>

// Problem constants (fixed by the dataset: B=256, D=H=512, lengths=128..383)
#define NN 65408
#define BP 256
#define DD 512
#define HH 512
#define GG 2048
#define TT 383
#define KK 512

// ---------------- device scratch ---------------------------------------------
__device__ __align__(16) float g_xW[(size_t)NN * GG];     // gate pre-acts (fp32)
__device__ __align__(16) float g_flat[(size_t)NN * HH];   // flat LSTM outputs (fp32)
__device__ __align__(16) float g_att[NN];
__device__ __align__(16) float g_logit[NN];
__device__ __align__(16) float g_seg[BP * HH];
// h in packed fp16 A-fragment layout, double-buffered
__device__ __align__(16) uint4 g_HF[2][16 * 32 * 32];
// W_hh packed fp16 B-fragment order
__device__ __align__(16) uint2 g_GWH[(size_t)GG * 128];
__device__ int      g_off[BP];
__device__ __align__(128) unsigned g_bar[8 * 128];

__device__ __forceinline__ float sigf(float x) { return 1.0f / (1.0f + expf(-x)); }

__device__ __forceinline__ uint32_t packh2(float a, float b) {
    __half2 h = __floats2half2_rn(a, b);
    uint32_t r; memcpy(&r, &h, 4); return r;
}
__device__ __forceinline__ float2 unpackh2(uint32_t u) {
    __half2 h; memcpy(&h, &u, 4);
    return __half22float2(h);
}
__device__ __forceinline__ uint32_t tanh2(uint32_t x) {
    uint32_t r; asm("tanh.approx.f16x2 %0, %1;" : "=r"(r) : "r"(x)); return r;
}
__device__ __forceinline__ void mma_f16(float* c,
                                        uint32_t a0, uint32_t a1, uint32_t a2, uint32_t a3,
                                        uint32_t b0, uint32_t b1) {
    asm volatile("mma.sync.aligned.m16n8k16.row.col.f32.f16.f16.f32 "
        "{%0,%1,%2,%3}, {%4,%5,%6,%7}, {%8,%9}, {%0,%1,%2,%3};"
        : "+f"(c[0]), "+f"(c[1]), "+f"(c[2]), "+f"(c[3])
        : "r"(a0), "r"(a1), "r"(a2), "r"(a3), "r"(b0), "r"(b1));
}
__device__ __forceinline__ void bar_arrive(unsigned* p) {
    asm volatile("red.release.gpu.global.add.u32 [%0], 1;" :: "l"(p) : "memory");
}
__device__ __forceinline__ unsigned bar_peek(const unsigned* p) {
    unsigned v;
    asm volatile("ld.acquire.gpu.global.u32 %0, [%1];" : "=r"(v) : "l"(p) : "memory");
    return v;
}
__device__ __forceinline__ uint4 ldcg16(const uint4* p) {
    uint4 v;
    asm volatile("ld.global.cg.v4.u32 {%0,%1,%2,%3}, [%4];"
        : "=r"(v.x), "=r"(v.y), "=r"(v.z), "=r"(v.w) : "l"(p));
    return v;
}

// =================== fp16 mma.sync NT GEMM: C = A @ B^T + bias ==============
// Optional fused logit: logit_out[row] += sum_col C[row,col]*logitW[col].
#define GP16 20
#define STAGE_U (128 * GP16)
#define GEMM_SMEM (4 * STAGE_U * 4)          // 40960 B

__global__ void __launch_bounds__(256)
tgemm_f16(const float* __restrict__ A, const float* __restrict__ Bm,
          const float* __restrict__ bias1, const float* __restrict__ bias2,
          float* __restrict__ C, int Ncols,
          const float* __restrict__ logitW, float* __restrict__ logit_out) {
    extern __shared__ __align__(16) uint32_t smu[];
    uint32_t* As[2] = { smu,           smu + 2 * STAGE_U };
    uint32_t* Bs[2] = { smu + STAGE_U, smu + 3 * STAGE_U };

    const int tid = threadIdx.x;
    const int wid = tid >> 5, lane = tid & 31;
    const int grp = lane >> 2, tig = lane & 3;
    const int warpM = wid >> 2, warpN = wid & 3;
    const size_t m0 = (size_t)blockIdx.y * 128;
    const int    n0 = blockIdx.x * 128;

    const int lrow = tid >> 1;
    const int lcb  = (tid & 1) * 16;
    const int jb   = (tid & 1) * 8;
    const float* Ag = A  + (m0 + lrow) * KK;
    const float* Bg = Bm + (size_t)(n0 + lrow) * KK;

    float4 ar[4], br[4];
    auto ldchunk = [&](int c) {
#pragma unroll
        for (int q = 0; q < 4; q++) {
            ar[q] = *(const float4*)&Ag[c * 32 + lcb + q * 4];
            br[q] = *(const float4*)&Bg[c * 32 + lcb + q * 4];
        }
    };
    auto stchunk = [&](int s) {
        uint32_t* a = As[s] + lrow * GP16 + jb;
        uint32_t* b = Bs[s] + lrow * GP16 + jb;
        uint4 va0 = make_uint4(packh2(ar[0].x, ar[0].y), packh2(ar[0].z, ar[0].w),
                               packh2(ar[1].x, ar[1].y), packh2(ar[1].z, ar[1].w));
        uint4 va1 = make_uint4(packh2(ar[2].x, ar[2].y), packh2(ar[2].z, ar[2].w),
                               packh2(ar[3].x, ar[3].y), packh2(ar[3].z, ar[3].w));
        uint4 vb0 = make_uint4(packh2(br[0].x, br[0].y), packh2(br[0].z, br[0].w),
                               packh2(br[1].x, br[1].y), packh2(br[1].z, br[1].w));
        uint4 vb1 = make_uint4(packh2(br[2].x, br[2].y), packh2(br[2].z, br[2].w),
                               packh2(br[3].x, br[3].y), packh2(br[3].z, br[3].w));
        *(uint4*)(a + 0) = va0; *(uint4*)(a + 4) = va1;
        *(uint4*)(b + 0) = vb0; *(uint4*)(b + 4) = vb1;
    };

    float acc[4][4][4];
#pragma unroll
    for (int i = 0; i < 4; i++)
#pragma unroll
        for (int j = 0; j < 4; j++)
#pragma unroll
            for (int k = 0; k < 4; k++) acc[i][j][k] = 0.f;

    ldchunk(0); stchunk(0);
    __syncthreads();

    for (int c = 0; c < KK / 32; c++) {
        const int s = c & 1;
        if (c + 1 < KK / 32) ldchunk(c + 1);

        const uint32_t* Aw = As[s] + (warpM * 64 + grp) * GP16;
        const uint32_t* Bw = Bs[s] + (warpN * 32 + grp) * GP16;
#pragma unroll
        for (int j0 = 0; j0 < 16; j0 += 8) {
            uint32_t af[4][4], bf[4][2];
#pragma unroll
            for (int mf = 0; mf < 4; mf++) {
                const uint32_t* p = Aw + mf * 16 * GP16 + j0;
                af[mf][0] = p[tig];
                af[mf][1] = p[8 * GP16 + tig];
                af[mf][2] = p[tig + 4];
                af[mf][3] = p[8 * GP16 + tig + 4];
            }
#pragma unroll
            for (int nf = 0; nf < 4; nf++) {
                const uint32_t* p = Bw + nf * 8 * GP16 + j0;
                bf[nf][0] = p[tig];
                bf[nf][1] = p[tig + 4];
            }
#pragma unroll
            for (int mf = 0; mf < 4; mf++)
#pragma unroll
                for (int nf = 0; nf < 4; nf++)
                    mma_f16(acc[mf][nf],
                            af[mf][0], af[mf][1], af[mf][2], af[mf][3],
                            bf[nf][0], bf[nf][1]);
        }
        __syncthreads();
        if (c + 1 < KK / 32) { stchunk((c + 1) & 1); __syncthreads(); }
    }

#pragma unroll
    for (int mf = 0; mf < 4; mf++) {
        size_t r0 = m0 + warpM * 64 + mf * 16 + grp;
        float p0 = 0.f, p1 = 0.f;
#pragma unroll
        for (int nf = 0; nf < 4; nf++) {
            int col = n0 + warpN * 32 + nf * 8 + 2 * tig;
            float b0 = bias1[col], b1 = bias1[col + 1];
            if (bias2) { b0 += bias2[col]; b1 += bias2[col + 1]; }
            float c00 = acc[mf][nf][0] + b0, c01 = acc[mf][nf][1] + b1;
            float c10 = acc[mf][nf][2] + b0, c11 = acc[mf][nf][3] + b1;
            *(float2*)&C[r0 * (size_t)Ncols + col]       = make_float2(c00, c01);
            *(float2*)&C[(r0 + 8) * (size_t)Ncols + col] = make_float2(c10, c11);
            if (logitW) {
                float w0 = logitW[col], w1 = logitW[col + 1];
                p0 = fmaf(c00, w0, fmaf(c01, w1, p0));
                p1 = fmaf(c10, w0, fmaf(c11, w1, p1));
            }
        }
        if (logitW) {
            p0 += __shfl_xor_sync(0xffffffffu, p0, 1);
            p0 += __shfl_xor_sync(0xffffffffu, p0, 2);
            p1 += __shfl_xor_sync(0xffffffffu, p1, 1);
            p1 += __shfl_xor_sync(0xffffffffu, p1, 2);
            if (tig == 0) {
                atomicAdd(&logit_out[r0], p0);
                atomicAdd(&logit_out[r0 + 8], p1);
            }
        }
    }
}

// ---------------- init --------------------------------------------------------
__global__ void k_init(const int* __restrict__ lengths) {
    int tid = blockIdx.x * blockDim.x + threadIdx.x;
    if (tid < 2 * 16 * 32 * 32 * 4) ((uint32_t*)g_HF)[tid] = 0u;
    if (tid < BP * HH) g_seg[tid] = 0.f;
    if (tid < NN) g_logit[tid] = 0.f;
    if (tid < 8 * 128) g_bar[tid] = 0u;
    if (tid == 0) {
        int acc = 0;
        for (int b = 0; b < BP; b++) { g_off[b] = acc; acc += lengths[b]; }
    }
}

// ---------------- prep: pack W_hh into fp16 B-fragment order ----------------
__global__ void k_prepw(const float* __restrict__ W) {
    int id = blockIdx.x * blockDim.x + threadIdx.x;
    if (id >= GG * 128) return;
    int n = id >> 7;
    int r = id & 127;
    int c = r >> 2, tig = r & 3;
    const float* wr = W + (size_t)n * KK + 16 * c;
    uint2 v;
    v.x = packh2(wr[2 * tig], wr[2 * tig + 1]);
    v.y = packh2(wr[2 * tig + 8], wr[2 * tig + 9]);
    g_GWH[id] = v;
}

// ---------------- persistent LSTM recurrence (fp16 mma, 512 thr) ------------
// FULL W slice resident in smem; epilogue activations via tanh.approx.f16x2
// (paired outputs: 5 MUFU per 2 outputs instead of 10).
#define WPITCH16 33
#define WH_BYTES (128 * WPITCH16 * 32)                 // 135168 B
#define HA_BYTES (2048 * 16)                           // 32768 B
#define GT_PITCH2 136
#define GT_BYTES (32 * GT_PITCH2 * 4)                  // 17408 B
#define PSM4 (WH_BYTES + HA_BYTES + GT_BYTES)          // 185344 B

__global__ void __launch_bounds__(512)
k_lstm_persist(const int* __restrict__ lengths) {
    extern __shared__ __align__(16) char smraw[];
    uint2* WH = (uint2*)smraw;
    uint4* HA = (uint4*)(smraw + WH_BYTES);
    float* GT = (float*)(smraw + WH_BYTES + HA_BYTES);

    __shared__ int len_s[32];
    __shared__ int off_s[32];
    __shared__ int s_tmax;

    const int tid = threadIdx.x;
    const int pg = blockIdx.x, cg = blockIdx.y;
    const int p0 = pg * 32, hc0 = cg * 32;
    const int wid = tid >> 5, lane = tid & 31;
    const int grp = lane >> 2, tig = lane & 3;
    const int warpM = wid >> 3, warpN = wid & 7;
    unsigned* barp = &g_bar[pg * 128];

    if (wid == 0) {
        int L = lengths[p0 + lane];
        len_s[lane] = L;
        off_s[lane] = g_off[p0 + lane];
        int m = L;
#pragma unroll
        for (int o = 16; o; o >>= 1) m = max(m, __shfl_xor_sync(0xffffffffu, m, o));
        if (lane == 0) s_tmax = m;
    }

    // ---- preload FULL W slice (128 rows x 512 k) as fp16 frags ----
#pragma unroll
    for (int i = 0; i < 16; i++) {
        int gidx = tid + i * 512;
        int lr = gidx >> 6;
        int rem = gidx & 63;
        int c = rem >> 1, hf = rem & 1;
        int n = (lr >> 5) * HH + hc0 + (lr & 31);
        const uint4* src = (const uint4*)g_GWH + ((size_t)(n * 32 + c) * 2 + hf);
        uint4* dst = (uint4*)WH + ((size_t)(lr * WPITCH16 + c) * 2 + hf);
        *dst = *src;
    }
    __syncthreads();
    const int tmax = s_tmax;

    const int lr0 = warpN * 16 + grp;
    const int lr1 = lr0 + 8;
    const uint2* W0p = WH + (size_t)lr0 * WPITCH16 * 4 + tig;
    const uint2* W1p = WH + (size_t)lr1 * WPITCH16 * 4 + tig;

    const int rA = 16 * warpM + grp;
    const uint4* HAw = HA + (size_t)warpM * 1024 + lane;

    const int ep[2] = { tid >> 5, (tid + 512) >> 5 };
    const int eh = tid & 31;
    float creg[2] = { 0.f, 0.f };

    const int kk = hc0 + eh;
    const int kc = kk >> 4, klo = kk & 15;
    const int ktig = (klo & 7) >> 1, ksub = klo & 1, khi = (klo >= 8);
    size_t hoff[2];
#pragma unroll
    for (int s = 0; s < 2; s++) {
        int pl = ep[s];
        int tile_g = pg * 2 + (pl >> 4);
        int r16 = pl & 15;
        int grp8 = r16 & 7, hiM = r16 >> 3;
        int slot = hiM + 2 * khi;
        hoff[s] = ((size_t)(tile_g * 32 + kc) * 32 + grp8 * 4 + ktig) * 16 + slot * 4 + ksub * 2;
    }

    float xg[2][4];
    bool  act[2];
    size_t fis[2];
    auto prefetch_xw = [&](int t) {
#pragma unroll
        for (int s = 0; s < 2; s++) {
            int p = ep[s];
            act[s] = (t < len_s[p]);
            if (act[s]) {
                fis[s] = (size_t)(off_s[p] + t);
                size_t xb = fis[s] * GG + hc0 + eh;
#pragma unroll
                for (int g = 0; g < 4; g++) xg[s][g] = __ldcg(&g_xW[xb + g * HH]);
            } else {
                fis[s] = 0;
                xg[s][0] = xg[s][1] = xg[s][2] = xg[s][3] = 0.f;
            }
        }
    };
    prefetch_xw(0);

    for (int t = 0; t < tmax; t++) {
        // ---- fill HA: coalesced copy of pre-packed fp16 h ----
        const uint4* hsrc = &g_HF[t & 1][(size_t)pg * 2048];
#pragma unroll
        for (int i = 0; i < 4; i++) {
            int idx = tid + i * 512;
            HA[idx] = ldcg16(hsrc + idx);
        }
        __syncthreads();

        // ---- 32x128x512 gates GEMM: fp16 m16n8k16, fp32 accum ----
        float acc[2][4];
#pragma unroll
        for (int i = 0; i < 2; i++)
#pragma unroll
            for (int j = 0; j < 4; j++) acc[i][j] = 0.f;

#pragma unroll 8
        for (int c = 0; c < 32; c++) {
            uint4 Af = HAw[c * 32];
            uint2 W0 = W0p[c * 4];
            uint2 W1 = W1p[c * 4];
            mma_f16(acc[0], Af.x, Af.y, Af.z, Af.w, W0.x, W0.y);
            mma_f16(acc[1], Af.x, Af.y, Af.z, Af.w, W1.x, W1.y);
        }

        // ---- gate exchange to smem ----
#pragma unroll
        for (int nf = 0; nf < 2; nf++) {
            int cb = warpN * 16 + nf * 8 + 2 * tig;
            *(float2*)&GT[rA * GT_PITCH2 + cb]       = make_float2(acc[nf][0], acc[nf][1]);
            *(float2*)&GT[(rA + 8) * GT_PITCH2 + cb] = make_float2(acc[nf][2], acc[nf][3]);
        }
        __syncthreads();

        // ---- epilogue: paired f16x2 activations (5 MUFU per 2 outputs) ----
        float ga[4], gb[4];
#pragma unroll
        for (int g = 0; g < 4; g++) {
            ga[g] = GT[ep[0] * GT_PITCH2 + g * 32 + eh] + xg[0][g];
            gb[g] = GT[ep[1] * GT_PITCH2 + g * 32 + eh] + xg[1][g];
        }
        float2 ti = unpackh2(tanh2(packh2(0.5f * ga[0], 0.5f * gb[0])));
        float2 tf = unpackh2(tanh2(packh2(0.5f * ga[1], 0.5f * gb[1])));
        float2 tg = unpackh2(tanh2(packh2(ga[2], gb[2])));
        float2 to = unpackh2(tanh2(packh2(0.5f * ga[3], 0.5f * gb[3])));
        float si0 = fmaf(ti.x, 0.5f, 0.5f), si1 = fmaf(ti.y, 0.5f, 0.5f);
        float sf0 = fmaf(tf.x, 0.5f, 0.5f), sf1 = fmaf(tf.y, 0.5f, 0.5f);
        float so0 = fmaf(to.x, 0.5f, 0.5f), so1 = fmaf(to.y, 0.5f, 0.5f);
        float cn0 = fmaf(sf0, creg[0], si0 * tg.x);
        float cn1 = fmaf(sf1, creg[1], si1 * tg.y);
        creg[0] = cn0; creg[1] = cn1;
        float2 tc = unpackh2(tanh2(packh2(cn0, cn1)));
        float hn[2] = { so0 * tc.x, so1 * tc.y };

        char* hdst = (char*)&g_HF[(t + 1) & 1][0];
        if (act[0]) *(__half*)(hdst + hoff[0]) = __float2half_rn(hn[0]);
        if (act[1]) *(__half*)(hdst + hoff[1]) = __float2half_rn(hn[1]);

        // ---- arrive (release), overlap flat stores + next xW prefetch ----
        __syncthreads();
        if (tid == 0) bar_arrive(barp);
        size_t fsave[2] = { fis[0], fis[1] };
        bool   asave[2] = { act[0], act[1] };
        float  hsave[2] = { hn[0], hn[1] };
        if (t + 1 < tmax) prefetch_xw(t + 1);
#pragma unroll
        for (int s = 0; s < 2; s++)
            if (asave[s]) g_flat[fsave[s] * HH + hc0 + eh] = hsave[s];
        if (tid == 0) {
            unsigned target = 16u * (unsigned)(t + 1);
            while (bar_peek(barp) < target) __nanosleep(32);
        }
        __syncthreads();
    }
}

// ---------------- attention gate (elementwise; logit pre-computed) ----------
__global__ void k_att(const float* __restrict__ fc2_b, const float* __restrict__ eps_u) {
    int n = blockIdx.x * blockDim.x + threadIdx.x;
    if (n >= NN) return;
    float logit = g_logit[n] + fc2_b[0];
    float eu = eps_u[n];
    float eps = (2.0f * 1e-4f - 1.0f) * eu + (1.0f - 1e-4f);
    float gate = logf(eps) - logf(1.0f - eps) + logit;
    g_att[n] = sigf(gate);
}

// ---------------- gated segment sum (8-way split + atomic accumulate) -------
__global__ void k_seg(const int* __restrict__ lengths) {
    int b = blockIdx.x;
    int chunk = blockIdx.y;
    int col = threadIdx.x;
    int off = g_off[b];
    int L = lengths[b];
    int r0 = (L * chunk) >> 3;
    int r1 = (L * (chunk + 1)) >> 3;
    float acc = 0.f;
    for (int r = r0; r < r1; r++) {
        int n = off + r;
        acc += g_flat[(size_t)n * HH + col] * g_att[n];
    }
    atomicAdd(&g_seg[(size_t)b * HH + col], acc);
}

// ---------------- final tiny MLP ---------------------------------------------
__global__ void k_final(const float* __restrict__ mlp1_W, const float* __restrict__ mlp1_b,
                        const float* __restrict__ mlp2_W, const float* __restrict__ mlp2_b,
                        float* __restrict__ out) {
    __shared__ float hidden[16];
    int b = blockIdx.x;
    int tid = threadIdx.x;
    int w = tid >> 5, lane = tid & 31;
    const float* seg = &g_seg[(size_t)b * HH];
    float s = 0.f;
#pragma unroll
    for (int k = lane; k < HH; k += 32) s += seg[k] * mlp1_W[(size_t)w * HH + k];
#pragma unroll
    for (int o = 16; o; o >>= 1) s += __shfl_xor_sync(0xffffffffu, s, o);
    if (lane == 0) hidden[w] = s + mlp1_b[w];
    __syncthreads();
    if (tid < 2) {
        float o = mlp2_b[tid];
#pragma unroll
        for (int j = 0; j < 16; j++) o += hidden[j] * mlp2_W[tid * 16 + j];
        out[b * 2 + tid] = o;
    }
}

// -----------------------------------------------------------------------------
extern "C" void kernel_launch(void* const* d_in, const int* in_sizes, int n_in,
                              void* d_out, int out_size) {
    const float* lstm_input = (const float*)d_in[0];
    const float* eps_u      = (const float*)d_in[1];
    const float* W_ih       = (const float*)d_in[2];
    const float* W_hh       = (const float*)d_in[3];
    const float* b_ih       = (const float*)d_in[4];
    const float* b_hh       = (const float*)d_in[5];
    const float* fc1_W      = (const float*)d_in[6];
    const float* fc1_b      = (const float*)d_in[7];
    const float* fc2_W      = (const float*)d_in[8];
    const float* fc2_b      = (const float*)d_in[9];
    const float* mlp1_W     = (const float*)d_in[10];
    const float* mlp1_b     = (const float*)d_in[11];
    const float* mlp2_W     = (const float*)d_in[12];
    const float* mlp2_b     = (const float*)d_in[13];
    const int*   lengths    = (const int*)d_in[14];

    float* out = (float*)d_out;
    float* passedZ = out + BP * 2;   // tuple order: final[256,2] then passed_Z[N,512]

    float *xw, *flat, *logit;
    cudaGetSymbolAddress((void**)&xw, g_xW);
    cudaGetSymbolAddress((void**)&flat, g_flat);
    cudaGetSymbolAddress((void**)&logit, g_logit);

    cudaFuncSetAttribute(tgemm_f16, cudaFuncAttributeMaxDynamicSharedMemorySize, GEMM_SMEM);
    cudaFuncSetAttribute(k_lstm_persist, cudaFuncAttributeMaxDynamicSharedMemorySize, PSM4);

    // 1. init states/offsets/barriers/logits
    k_init<<<(2 * 16 * 32 * 32 * 4 + 255) / 256, 256>>>(lengths);

    // 2. pack W_hh into fp16 fragment order
    k_prepw<<<(GG * 128 + 255) / 256, 256>>>(W_hh);

    // 3. xW = X @ W_ih^T + b_ih + b_hh   (fp16 MMA, fp32 accum/store)
    tgemm_f16<<<dim3(GG / 128, NN / 128), 256, GEMM_SMEM>>>(
        lstm_input, W_ih, b_ih, b_hh, xw, GG, nullptr, nullptr);

    // 4. full LSTM recurrence in ONE persistent launch
    k_lstm_persist<<<dim3(8, 16), 512, PSM4>>>(lengths);

    // 5. passed_Z = flat @ fc1_W^T + fc1_b -> d_out, with FUSED att-logit dot
    tgemm_f16<<<dim3(DD / 128, NN / 128), 256, GEMM_SMEM>>>(
        flat, fc1_W, fc1_b, nullptr, passedZ, DD, fc2_W, logit);

    // 6. attention gate per flat row (elementwise)
    k_att<<<(NN + 255) / 256, 256>>>(fc2_b, eps_u);

    // 7. gated per-person segment sum (8-way parallel)
    k_seg<<<dim3(BP, 8), HH>>>(lengths);

    // 8. final MLP -> out[0:512]
    k_final<<<BP, 512>>>(mlp1_W, mlp1_b, mlp2_W, mlp2_b, out);
}